// round 6
// baseline (speedup 1.0000x reference)
#include <cuda_runtime.h>
#include <cuda_fp16.h>
#include <cstdint>

// ============================================================================
// TimeEmbedder: temb(t) -> standardize -> silu(x@W1+b1) -> @W2+b2
// FP16 mma.sync m16n8k16 (fp32 accum). CTA tile 128x128x64, 4 warps,
// 3-stage cp.async (issues interleaved into k-steps), 2 CTAs/SM.
// ============================================================================

#define DIM     1024
#define BATCH   32768
#define NOUT    4096   // DIM*EXP

// ---------------- scratch (device globals; no allocations allowed) ----------
__device__ __half g_temb[(size_t)BATCH * DIM];   // fp16 A of GEMM1 (64 MB)
__device__ __half g_w1t[(size_t)NOUT * DIM];     // [N,K] K-major fp16 (8 MB)
__device__ __half g_w2t[(size_t)NOUT * NOUT];    // [N,K] K-major fp16 (32 MB)
__device__ __half g_h[(size_t)BATCH * NOUT];     // fp16 A of GEMM2 (256 MB)
__device__ float  g_freq[DIM / 2];

// ---------------- helpers ----------------------------------------------------
__device__ __forceinline__ uint32_t smem_u32(const void* p) {
    uint32_t a;
    asm("{ .reg .u64 t; cvta.to.shared.u64 t, %1; cvt.u32.u64 %0, t; }" : "=r"(a) : "l"(p));
    return a;
}
__device__ __forceinline__ uint32_t swz128(uint32_t o) { return o ^ ((o >> 3) & 0x70u); }
__device__ __forceinline__ void cp_async16(uint32_t dst, const void* src) {
    asm volatile("cp.async.cg.shared.global [%0], [%1], 16;" :: "r"(dst), "l"(src));
}
__device__ __forceinline__ void cp_commit() { asm volatile("cp.async.commit_group;"); }

__device__ __forceinline__ void ldsm_x4(uint32_t* r, uint32_t addr) {
    asm volatile("ldmatrix.sync.aligned.m8n8.x4.shared.b16 {%0,%1,%2,%3}, [%4];"
                 : "=r"(r[0]), "=r"(r[1]), "=r"(r[2]), "=r"(r[3]) : "r"(addr));
}
__device__ __forceinline__ void mma_f16(float* c, const uint32_t* a, uint32_t b0, uint32_t b1) {
    asm volatile("mma.sync.aligned.m16n8k16.row.col.f32.f16.f16.f32 "
                 "{%0,%1,%2,%3}, {%4,%5,%6,%7}, {%8,%9}, {%0,%1,%2,%3};"
                 : "+f"(c[0]), "+f"(c[1]), "+f"(c[2]), "+f"(c[3])
                 : "r"(a[0]), "r"(a[1]), "r"(a[2]), "r"(a[3]), "r"(b0), "r"(b1));
}

// ============================================================================
// Kernel 0: geometric frequencies
// ============================================================================
__global__ void freq_kernel() {
    int i = threadIdx.x;
    if (i < DIM / 2) {
        float ef = (float)i / 511.0f;
        g_freq[i] = (float)pow(1e-4, (double)ef);
    }
}

// ============================================================================
// Kernel 1: positional embedding + standardization -> fp16 (packed stores)
// ============================================================================
__global__ void __launch_bounds__(512) temb_kernel(const float* __restrict__ t) {
    __shared__ float s_sum[16], s_ssq[16];
    __shared__ float s_mean, s_rstd;
    int b = blockIdx.x, i = threadIdx.x;

    float x = t[b] * 1000.0f;
    float p = x * g_freq[i];                      // fp32 angle, matches reference
    double pd = (double)p;
    double k  = rint(pd * 0.15915494309189535);
    double r  = fma(-k, 6.283185307179586, pd);
    float rf = (float)r;
    float c = cosf(rf), s = sinf(rf);

    float sum = c + s;
    float ssq = c * c + s * s;
    #pragma unroll
    for (int o = 16; o > 0; o >>= 1) {
        sum += __shfl_xor_sync(0xFFFFFFFFu, sum, o);
        ssq += __shfl_xor_sync(0xFFFFFFFFu, ssq, o);
    }
    if ((i & 31) == 0) { s_sum[i >> 5] = sum; s_ssq[i >> 5] = ssq; }
    __syncthreads();
    if (i == 0) {
        float S = 0.f, Q = 0.f;
        #pragma unroll
        for (int w = 0; w < 16; w++) { S += s_sum[w]; Q += s_ssq[w]; }
        float mean = S / (float)DIM;
        float var  = (Q - S * S / (float)DIM) / (float)(DIM - 1);
        s_mean = mean;
        s_rstd = rsqrtf(var);
    }
    __syncthreads();
    float mean = s_mean, rstd = s_rstd;
    float cn = (c - mean) * rstd;
    float sn = (s - mean) * rstd;
    float cn1 = __shfl_down_sync(0xFFFFFFFFu, cn, 1);
    float sn1 = __shfl_down_sync(0xFFFFFFFFu, sn, 1);
    if (!(i & 1)) {
        size_t base = (size_t)b * DIM;
        *(__half2*)&g_temb[base + i] =
            __halves2half2(__float2half_rn(cn), __float2half_rn(cn1));
        *(__half2*)&g_temb[base + 512 + i] =
            __halves2half2(__float2half_rn(sn), __float2half_rn(sn1));
    }
}

// ============================================================================
// Kernel 2: W [K,N] row-major fp32 -> WT [N,K] K-major fp16
// ============================================================================
__global__ void transpose_kernel(const float* __restrict__ src, int K, int N, int which) {
    __half* dst = which ? g_w2t : g_w1t;
    __shared__ float tile[32][33];
    int n0 = blockIdx.x * 32, k0 = blockIdx.y * 32;
    int tx = threadIdx.x, ty = threadIdx.y;
    #pragma unroll
    for (int i = 0; i < 32; i += 8)
        tile[ty + i][tx] = src[(size_t)(k0 + ty + i) * N + (n0 + tx)];
    __syncthreads();
    #pragma unroll
    for (int i = 0; i < 32; i += 8)
        dst[(size_t)(n0 + ty + i) * K + (k0 + tx)] = __float2half_rn(tile[tx][ty + i]);
}

// ============================================================================
// Kernel 3: FP16 mma.sync GEMM. C[m,n] = sum_k A[m,k]*Bt[n,k] (+bias, silu)
// CTA 128x128x64, 4 warps (warp 64x64), 3-stage cp.async, 2 CTAs/SM.
// cp.async issues for stage kt+2 are interleaved into the k-step loop.
// ============================================================================
#define BM 128
#define BN 128
#define BK 64
#define STAGES 3
#define ASTAGE (BM * BK * 2)            // 16 KB
#define BSTAGE (BN * BK * 2)            // 16 KB
#define STAGE_BYTES (ASTAGE + BSTAGE)   // 32 KB
#define DYN_SMEM (STAGES * STAGE_BYTES) // 96 KB

template <int KTOT, bool PHASE1>
__global__ void __launch_bounds__(128, 2)
gemm_kernel(const float* __restrict__ bias, float* __restrict__ Cout) {
    const __half* A  = PHASE1 ? g_temb : g_h;
    const __half* Bt = PHASE1 ? g_w1t  : g_w2t;

    extern __shared__ char dynsmem[];
    __shared__ float s_bias[BN];

    const int tid  = threadIdx.x;
    const int wid  = tid >> 5;
    const int lane = tid & 31;
    const int n0 = blockIdx.x * BN;
    const int m0 = blockIdx.y * BM;
    const int warp_m = (wid & 1) * 64;   // 0 / 64
    const int warp_n = (wid >> 1) * 64;  // 0 / 64

    const uint32_t dyn = smem_u32(dynsmem);

    if (tid < BN) s_bias[tid] = bias[n0 + tid];

    // ---- per-thread gmem->smem load plan (16B chunks = 8 halves) ----
    const char* Ab = (const char*)A;
    const char* Bb = (const char*)Bt;
    uint32_t offA[8], dA[8], offB[8], dB[8];
    #pragma unroll
    for (int j = 0; j < 8; j++) {
        uint32_t cid = (uint32_t)j * 128u + (uint32_t)tid;
        uint32_t row = cid >> 3, kc = cid & 7;
        offA[j] = (uint32_t)(m0 + row) * (uint32_t)KTOT * 2u + kc * 16u;
        dA[j]   = swz128(row * 128u + kc * 16u);
        offB[j] = (uint32_t)(n0 + row) * (uint32_t)KTOT * 2u + kc * 16u;
        dB[j]   = (uint32_t)ASTAGE + swz128(row * 128u + kc * 16u);
    }

    // ---- ldmatrix address precompute ----
    const uint32_t lane16 = lane & 15;
    const uint32_t hiA = (lane >> 4) & 1;
    uint32_t aRow[4], aXor[4];
    #pragma unroll
    for (int mt = 0; mt < 4; mt++) {
        uint32_t r = (uint32_t)(warp_m + mt * 16) + lane16;
        aRow[mt] = r * 128u;
        aXor[mt] = r & 7u;
    }
    const uint32_t nrl = (lane & 7) | ((lane >> 1) & 8);
    const uint32_t hiB = (lane >> 3) & 1;
    uint32_t bRow[4], bXor[4];
    #pragma unroll
    for (int p = 0; p < 4; p++) {
        uint32_t r = (uint32_t)(warp_n + p * 16) + nrl;
        bRow[p] = r * 128u;
        bXor[p] = r & 7u;
    }

    float c[4][8][4];
    #pragma unroll
    for (int mt = 0; mt < 4; mt++)
        #pragma unroll
        for (int nt = 0; nt < 8; nt++)
            #pragma unroll
            for (int i = 0; i < 4; i++) c[mt][nt][i] = 0.0f;

    const int nk = KTOT / BK;

    // ---- prologue: issue stages 0..STAGES-2 ----
    #pragma unroll
    for (int j = 0; j < STAGES - 1; j++) {
        uint32_t sb = dyn + (uint32_t)j * STAGE_BYTES;
        #pragma unroll
        for (int i = 0; i < 8; i++) cp_async16(sb + dA[i], Ab + offA[i]);
        #pragma unroll
        for (int i = 0; i < 8; i++) cp_async16(sb + dB[i], Bb + offB[i]);
        #pragma unroll
        for (int i = 0; i < 8; i++) { offA[i] += 128u; offB[i] += 128u; }
        cp_commit();
    }

    // fragment double buffers
    uint32_t a[2][4][4], b[2][4][4];

    #pragma unroll 3
    for (int kt = 0; kt < nk; kt++) {
        asm volatile("cp.async.wait_group %0;" :: "n"(STAGES - 2));
        __syncthreads();

        const bool do_load = (kt + STAGES - 1 < nk);
        uint32_t sbn = dyn + (uint32_t)((kt + STAGES - 1) % STAGES) * STAGE_BYTES;
        uint32_t sA  = dyn + (uint32_t)(kt % STAGES) * STAGE_BYTES;
        uint32_t sB  = sA + ASTAGE;

        // ---- preload k-step 0 fragments (tensor path starts immediately) ----
        #pragma unroll
        for (int mt = 0; mt < 4; mt++) {
            uint32_t col16 = hiA ^ aXor[mt];
            ldsm_x4(a[0][mt], sA + aRow[mt] + (col16 << 4));
        }
        #pragma unroll
        for (int p = 0; p < 4; p++) {
            uint32_t col16 = hiB ^ bXor[p];
            ldsm_x4(b[0][p], sB + bRow[p] + (col16 << 4));
        }

        // ---- pipelined k-steps: prefetch ks+1 frags + 4 interleaved cp.async ----
        #pragma unroll
        for (int ks = 0; ks < 4; ks++) {
            const int cur = ks & 1, nxt = cur ^ 1;
            if (ks < 3) {
                #pragma unroll
                for (int mt = 0; mt < 4; mt++) {
                    uint32_t col16 = ((uint32_t)((ks + 1) * 2) + hiA) ^ aXor[mt];
                    ldsm_x4(a[nxt][mt], sA + aRow[mt] + (col16 << 4));
                }
                #pragma unroll
                for (int p = 0; p < 4; p++) {
                    uint32_t col16 = ((uint32_t)((ks + 1) * 2) + hiB) ^ bXor[p];
                    ldsm_x4(b[nxt][p], sB + bRow[p] + (col16 << 4));
                }
            }
            // interleave 4 of the 16 next-stage loads into this k-step
            if (do_load) {
                if (ks < 2) {
                    #pragma unroll
                    for (int i = 0; i < 4; i++) {
                        const int j = ks * 4 + i;
                        cp_async16(sbn + dA[j], Ab + offA[j]);
                    }
                } else {
                    #pragma unroll
                    for (int i = 0; i < 4; i++) {
                        const int j = (ks - 2) * 4 + i;
                        cp_async16(sbn + dB[j], Bb + offB[j]);
                    }
                }
            }
            #pragma unroll
            for (int mt = 0; mt < 4; mt++) {
                #pragma unroll
                for (int nt = 0; nt < 8; nt++) {
                    const int p = nt >> 1;
                    if (nt & 1) mma_f16(c[mt][nt], a[cur][mt], b[cur][p][2], b[cur][p][3]);
                    else        mma_f16(c[mt][nt], a[cur][mt], b[cur][p][0], b[cur][p][1]);
                }
            }
        }
        if (do_load) {
            #pragma unroll
            for (int i = 0; i < 8; i++) { offA[i] += 128u; offB[i] += 128u; }
        }
        cp_commit();
    }
    __syncthreads();   // also covers s_bias visibility

    // ---- epilogue ----
    const int ncol0 = warp_n + (lane & 3) * 2;
    #pragma unroll
    for (int mt = 0; mt < 4; mt++) {
        int r0 = m0 + warp_m + mt * 16 + (lane >> 2);
        #pragma unroll
        for (int nt = 0; nt < 8; nt++) {
            float bv0 = s_bias[ncol0 + nt * 8];
            float bv1 = s_bias[ncol0 + nt * 8 + 1];
            float v0 = c[mt][nt][0] + bv0;
            float v1 = c[mt][nt][1] + bv1;
            float v2 = c[mt][nt][2] + bv0;
            float v3 = c[mt][nt][3] + bv1;
            if (PHASE1) {
                v0 = v0 / (1.0f + expf(-v0));
                v1 = v1 / (1.0f + expf(-v1));
                v2 = v2 / (1.0f + expf(-v2));
                v3 = v3 / (1.0f + expf(-v3));
                __half* row0 = g_h + (size_t)r0 * NOUT + (n0 + ncol0);
                __half* row1 = row0 + (size_t)8 * NOUT;
                *(__half2*)(row0 + nt * 8) =
                    __halves2half2(__float2half_rn(v0), __float2half_rn(v1));
                *(__half2*)(row1 + nt * 8) =
                    __halves2half2(__float2half_rn(v2), __float2half_rn(v3));
            } else {
                float* row0 = Cout + (size_t)r0 * NOUT + (n0 + ncol0);
                float* row1 = row0 + (size_t)8 * NOUT;
                __stcs((float2*)(row0 + nt * 8), make_float2(v0, v1));
                __stcs((float2*)(row1 + nt * 8), make_float2(v2, v3));
            }
        }
    }
}

// ============================================================================
// host launcher
// ============================================================================
extern "C" void kernel_launch(void* const* d_in, const int* in_sizes, int n_in,
                              void* d_out, int out_size) {
    const float* t  = (const float*)d_in[0];
    const float* W1 = (const float*)d_in[1];
    const float* b1 = (const float*)d_in[2];
    const float* W2 = (const float*)d_in[3];
    const float* b2 = (const float*)d_in[4];
    float* out = (float*)d_out;

    cudaFuncSetAttribute(gemm_kernel<DIM, true>,
                         cudaFuncAttributeMaxDynamicSharedMemorySize, DYN_SMEM);
    cudaFuncSetAttribute(gemm_kernel<NOUT, false>,
                         cudaFuncAttributeMaxDynamicSharedMemorySize, DYN_SMEM);

    freq_kernel<<<1, 512>>>();
    temb_kernel<<<BATCH, 512>>>(t);

    dim3 tb(32, 8);
    transpose_kernel<<<dim3(NOUT / 32, DIM / 32), tb>>>(W1, DIM, NOUT, 0);
    transpose_kernel<<<dim3(NOUT / 32, NOUT / 32), tb>>>(W2, NOUT, NOUT, 1);

    dim3 grid(NOUT / BN, BATCH / BM);   // (32, 256)
    gemm_kernel<DIM, true><<<grid, 128, DYN_SMEM>>>(b1, nullptr);
    gemm_kernel<NOUT, false><<<grid, 128, DYN_SMEM>>>(b2, out);
}

// round 7
// speedup vs baseline: 1.4952x; 1.4952x over previous
#include <cuda_runtime.h>
#include <cuda_fp16.h>
#include <cstdint>

// ============================================================================
// TimeEmbedder: temb(t) -> standardize -> silu(x@W1+b1) -> @W2+b2
// FP16 mma.sync m16n8k16 (fp32 accum). CTA tile 128x128x64, 4 warps,
// 3-stage cp.async, 2 CTAs/SM for cross-CTA latency hiding. (R5 structure.)
// ============================================================================

#define DIM     1024
#define BATCH   32768
#define NOUT    4096   // DIM*EXP

// ---------------- scratch (device globals; no allocations allowed) ----------
__device__ __half g_temb[(size_t)BATCH * DIM];   // fp16 A of GEMM1 (64 MB)
__device__ __half g_w1t[(size_t)NOUT * DIM];     // [N,K] K-major fp16 (8 MB)
__device__ __half g_w2t[(size_t)NOUT * NOUT];    // [N,K] K-major fp16 (32 MB)
__device__ __half g_h[(size_t)BATCH * NOUT];     // fp16 A of GEMM2 (256 MB)
__device__ float  g_freq[DIM / 2];

// ---------------- helpers ----------------------------------------------------
__device__ __forceinline__ uint32_t smem_u32(const void* p) {
    uint32_t a;
    asm("{ .reg .u64 t; cvta.to.shared.u64 t, %1; cvt.u32.u64 %0, t; }" : "=r"(a) : "l"(p));
    return a;
}
__device__ __forceinline__ uint32_t swz128(uint32_t o) { return o ^ ((o >> 3) & 0x70u); }
__device__ __forceinline__ void cp_async16(uint32_t dst, const void* src) {
    asm volatile("cp.async.cg.shared.global [%0], [%1], 16;" :: "r"(dst), "l"(src));
}
__device__ __forceinline__ void cp_commit() { asm volatile("cp.async.commit_group;"); }

__device__ __forceinline__ void ldsm_x4(uint32_t* r, uint32_t addr) {
    asm volatile("ldmatrix.sync.aligned.m8n8.x4.shared.b16 {%0,%1,%2,%3}, [%4];"
                 : "=r"(r[0]), "=r"(r[1]), "=r"(r[2]), "=r"(r[3]) : "r"(addr));
}
__device__ __forceinline__ void mma_f16(float* c, const uint32_t* a, uint32_t b0, uint32_t b1) {
    asm volatile("mma.sync.aligned.m16n8k16.row.col.f32.f16.f16.f32 "
                 "{%0,%1,%2,%3}, {%4,%5,%6,%7}, {%8,%9}, {%0,%1,%2,%3};"
                 : "+f"(c[0]), "+f"(c[1]), "+f"(c[2]), "+f"(c[3])
                 : "r"(a[0]), "r"(a[1]), "r"(a[2]), "r"(a[3]), "r"(b0), "r"(b1));
}

// ============================================================================
// Kernel 0: geometric frequencies
// ============================================================================
__global__ void freq_kernel() {
    int i = threadIdx.x;
    if (i < DIM / 2) {
        float ef = (float)i / 511.0f;
        g_freq[i] = (float)pow(1e-4, (double)ef);
    }
}

// ============================================================================
// Kernel 1: positional embedding + standardization -> fp16 (packed stores)
// ============================================================================
__global__ void __launch_bounds__(512) temb_kernel(const float* __restrict__ t) {
    __shared__ float s_sum[16], s_ssq[16];
    __shared__ float s_mean, s_rstd;
    int b = blockIdx.x, i = threadIdx.x;

    float x = t[b] * 1000.0f;
    float p = x * g_freq[i];                      // fp32 angle, matches reference
    double pd = (double)p;
    double k  = rint(pd * 0.15915494309189535);
    double r  = fma(-k, 6.283185307179586, pd);
    float rf = (float)r;
    float c = cosf(rf), s = sinf(rf);

    float sum = c + s;
    float ssq = c * c + s * s;
    #pragma unroll
    for (int o = 16; o > 0; o >>= 1) {
        sum += __shfl_xor_sync(0xFFFFFFFFu, sum, o);
        ssq += __shfl_xor_sync(0xFFFFFFFFu, ssq, o);
    }
    if ((i & 31) == 0) { s_sum[i >> 5] = sum; s_ssq[i >> 5] = ssq; }
    __syncthreads();
    if (i == 0) {
        float S = 0.f, Q = 0.f;
        #pragma unroll
        for (int w = 0; w < 16; w++) { S += s_sum[w]; Q += s_ssq[w]; }
        float mean = S / (float)DIM;
        float var  = (Q - S * S / (float)DIM) / (float)(DIM - 1);
        s_mean = mean;
        s_rstd = rsqrtf(var);
    }
    __syncthreads();
    float mean = s_mean, rstd = s_rstd;
    float cn = (c - mean) * rstd;
    float sn = (s - mean) * rstd;
    float cn1 = __shfl_down_sync(0xFFFFFFFFu, cn, 1);
    float sn1 = __shfl_down_sync(0xFFFFFFFFu, sn, 1);
    if (!(i & 1)) {
        size_t base = (size_t)b * DIM;
        *(__half2*)&g_temb[base + i] =
            __halves2half2(__float2half_rn(cn), __float2half_rn(cn1));
        *(__half2*)&g_temb[base + 512 + i] =
            __halves2half2(__float2half_rn(sn), __float2half_rn(sn1));
    }
}

// ============================================================================
// Kernel 2: W [K,N] row-major fp32 -> WT [N,K] K-major fp16
// ============================================================================
__global__ void transpose_kernel(const float* __restrict__ src, int K, int N, int which) {
    __half* dst = which ? g_w2t : g_w1t;
    __shared__ float tile[32][33];
    int n0 = blockIdx.x * 32, k0 = blockIdx.y * 32;
    int tx = threadIdx.x, ty = threadIdx.y;
    #pragma unroll
    for (int i = 0; i < 32; i += 8)
        tile[ty + i][tx] = src[(size_t)(k0 + ty + i) * N + (n0 + tx)];
    __syncthreads();
    #pragma unroll
    for (int i = 0; i < 32; i += 8)
        dst[(size_t)(n0 + ty + i) * K + (k0 + tx)] = __float2half_rn(tile[tx][ty + i]);
}

// ============================================================================
// Kernel 3: FP16 mma.sync GEMM. C[m,n] = sum_k A[m,k]*Bt[n,k] (+bias, silu)
// CTA 128x128x64, 4 warps (warp 64x64), 3-stage cp.async, 2 CTAs/SM.
// ============================================================================
#define BM 128
#define BN 128
#define BK 64
#define STAGES 3
#define ASTAGE (BM * BK * 2)            // 16 KB
#define BSTAGE (BN * BK * 2)            // 16 KB
#define STAGE_BYTES (ASTAGE + BSTAGE)   // 32 KB
#define DYN_SMEM (STAGES * STAGE_BYTES) // 96 KB

template <int KTOT, bool PHASE1>
__global__ void __launch_bounds__(128, 2)
gemm_kernel(const float* __restrict__ bias, float* __restrict__ Cout) {
    const __half* A  = PHASE1 ? g_temb : g_h;
    const __half* Bt = PHASE1 ? g_w1t  : g_w2t;

    extern __shared__ char dynsmem[];
    __shared__ float s_bias[BN];

    const int tid  = threadIdx.x;
    const int wid  = tid >> 5;
    const int lane = tid & 31;
    const int n0 = blockIdx.x * BN;
    const int m0 = blockIdx.y * BM;
    const int warp_m = (wid & 1) * 64;   // 0 / 64
    const int warp_n = (wid >> 1) * 64;  // 0 / 64

    const uint32_t dyn = smem_u32(dynsmem);

    if (tid < BN) s_bias[tid] = bias[n0 + tid];

    // ---- per-thread gmem->smem load plan (16B chunks = 8 halves) ----
    // A: 128 rows x 8 chunks = 1024 -> 8/thread ; B same
    const char* Ab = (const char*)A;
    const char* Bb = (const char*)Bt;
    uint32_t offA[8], dA[8], offB[8], dB[8];
    #pragma unroll
    for (int j = 0; j < 8; j++) {
        uint32_t cid = (uint32_t)j * 128u + (uint32_t)tid;
        uint32_t row = cid >> 3, kc = cid & 7;
        offA[j] = (uint32_t)(m0 + row) * (uint32_t)KTOT * 2u + kc * 16u;
        dA[j]   = swz128(row * 128u + kc * 16u);
        offB[j] = (uint32_t)(n0 + row) * (uint32_t)KTOT * 2u + kc * 16u;
        dB[j]   = (uint32_t)ASTAGE + swz128(row * 128u + kc * 16u);
    }

    // ---- ldmatrix address precompute ----
    const uint32_t lane16 = lane & 15;
    const uint32_t hiA = (lane >> 4) & 1;
    uint32_t aRow[4], aXor[4];
    #pragma unroll
    for (int mt = 0; mt < 4; mt++) {
        uint32_t r = (uint32_t)(warp_m + mt * 16) + lane16;
        aRow[mt] = r * 128u;
        aXor[mt] = r & 7u;
    }
    const uint32_t nrl = (lane & 7) | ((lane >> 1) & 8);
    const uint32_t hiB = (lane >> 3) & 1;
    uint32_t bRow[4], bXor[4];
    #pragma unroll
    for (int p = 0; p < 4; p++) {
        uint32_t r = (uint32_t)(warp_n + p * 16) + nrl;
        bRow[p] = r * 128u;
        bXor[p] = r & 7u;
    }

    float c[4][8][4];
    #pragma unroll
    for (int mt = 0; mt < 4; mt++)
        #pragma unroll
        for (int nt = 0; nt < 8; nt++)
            #pragma unroll
            for (int i = 0; i < 4; i++) c[mt][nt][i] = 0.0f;

    const int nk = KTOT / BK;

    // ---- prologue: issue stages 0..STAGES-2 ----
    #pragma unroll
    for (int j = 0; j < STAGES - 1; j++) {
        uint32_t sb = dyn + (uint32_t)j * STAGE_BYTES;
        #pragma unroll
        for (int i = 0; i < 8; i++) cp_async16(sb + dA[i], Ab + offA[i]);
        #pragma unroll
        for (int i = 0; i < 8; i++) cp_async16(sb + dB[i], Bb + offB[i]);
        #pragma unroll
        for (int i = 0; i < 8; i++) { offA[i] += 128u; offB[i] += 128u; }
        cp_commit();
    }

    // fragment double buffers
    uint32_t a[2][4][4], b[2][4][4];

    #pragma unroll 4
    for (int kt = 0; kt < nk; kt++) {
        asm volatile("cp.async.wait_group %0;" :: "n"(STAGES - 2));
        __syncthreads();

        // issue loads for stage kt+STAGES-1 into the buffer freed last iter
        if (kt + STAGES - 1 < nk) {
            uint32_t sb = dyn + (uint32_t)((kt + STAGES - 1) % STAGES) * STAGE_BYTES;
            #pragma unroll
            for (int i = 0; i < 8; i++) cp_async16(sb + dA[i], Ab + offA[i]);
            #pragma unroll
            for (int i = 0; i < 8; i++) cp_async16(sb + dB[i], Bb + offB[i]);
            #pragma unroll
            for (int i = 0; i < 8; i++) { offA[i] += 128u; offB[i] += 128u; }
        }
        cp_commit();

        uint32_t sA = dyn + (uint32_t)(kt % STAGES) * STAGE_BYTES;
        uint32_t sB = sA + ASTAGE;

        // ---- preload k-step 0 fragments ----
        #pragma unroll
        for (int mt = 0; mt < 4; mt++) {
            uint32_t col16 = hiA ^ aXor[mt];
            ldsm_x4(a[0][mt], sA + aRow[mt] + (col16 << 4));
        }
        #pragma unroll
        for (int p = 0; p < 4; p++) {
            uint32_t col16 = hiB ^ bXor[p];
            ldsm_x4(b[0][p], sB + bRow[p] + (col16 << 4));
        }

        // ---- pipelined k-steps: prefetch ks+1 while computing ks ----
        #pragma unroll
        for (int ks = 0; ks < 4; ks++) {
            const int cur = ks & 1, nxt = cur ^ 1;
            if (ks < 3) {
                #pragma unroll
                for (int mt = 0; mt < 4; mt++) {
                    uint32_t col16 = ((uint32_t)((ks + 1) * 2) + hiA) ^ aXor[mt];
                    ldsm_x4(a[nxt][mt], sA + aRow[mt] + (col16 << 4));
                }
                #pragma unroll
                for (int p = 0; p < 4; p++) {
                    uint32_t col16 = ((uint32_t)((ks + 1) * 2) + hiB) ^ bXor[p];
                    ldsm_x4(b[nxt][p], sB + bRow[p] + (col16 << 4));
                }
            }
            #pragma unroll
            for (int mt = 0; mt < 4; mt++) {
                #pragma unroll
                for (int nt = 0; nt < 8; nt++) {
                    const int p = nt >> 1;
                    if (nt & 1) mma_f16(c[mt][nt], a[cur][mt], b[cur][p][2], b[cur][p][3]);
                    else        mma_f16(c[mt][nt], a[cur][mt], b[cur][p][0], b[cur][p][1]);
                }
            }
        }
    }
    __syncthreads();   // also covers s_bias visibility

    // ---- epilogue ----
    const int ncol0 = warp_n + (lane & 3) * 2;
    #pragma unroll
    for (int mt = 0; mt < 4; mt++) {
        int r0 = m0 + warp_m + mt * 16 + (lane >> 2);
        #pragma unroll
        for (int nt = 0; nt < 8; nt++) {
            float bv0 = s_bias[ncol0 + nt * 8];
            float bv1 = s_bias[ncol0 + nt * 8 + 1];
            float v0 = c[mt][nt][0] + bv0;
            float v1 = c[mt][nt][1] + bv1;
            float v2 = c[mt][nt][2] + bv0;
            float v3 = c[mt][nt][3] + bv1;
            if (PHASE1) {
                v0 = v0 / (1.0f + expf(-v0));
                v1 = v1 / (1.0f + expf(-v1));
                v2 = v2 / (1.0f + expf(-v2));
                v3 = v3 / (1.0f + expf(-v3));
                __half* row0 = g_h + (size_t)r0 * NOUT + (n0 + ncol0);
                __half* row1 = row0 + (size_t)8 * NOUT;
                *(__half2*)(row0 + nt * 8) =
                    __halves2half2(__float2half_rn(v0), __float2half_rn(v1));
                *(__half2*)(row1 + nt * 8) =
                    __halves2half2(__float2half_rn(v2), __float2half_rn(v3));
            } else {
                float* row0 = Cout + (size_t)r0 * NOUT + (n0 + ncol0);
                float* row1 = row0 + (size_t)8 * NOUT;
                __stcs((float2*)(row0 + nt * 8), make_float2(v0, v1));
                __stcs((float2*)(row1 + nt * 8), make_float2(v2, v3));
            }
        }
    }
}

// ============================================================================
// host launcher
// ============================================================================
extern "C" void kernel_launch(void* const* d_in, const int* in_sizes, int n_in,
                              void* d_out, int out_size) {
    const float* t  = (const float*)d_in[0];
    const float* W1 = (const float*)d_in[1];
    const float* b1 = (const float*)d_in[2];
    const float* W2 = (const float*)d_in[3];
    const float* b2 = (const float*)d_in[4];
    float* out = (float*)d_out;

    cudaFuncSetAttribute(gemm_kernel<DIM, true>,
                         cudaFuncAttributeMaxDynamicSharedMemorySize, DYN_SMEM);
    cudaFuncSetAttribute(gemm_kernel<NOUT, false>,
                         cudaFuncAttributeMaxDynamicSharedMemorySize, DYN_SMEM);

    freq_kernel<<<1, 512>>>();
    temb_kernel<<<BATCH, 512>>>(t);

    dim3 tb(32, 8);
    transpose_kernel<<<dim3(NOUT / 32, DIM / 32), tb>>>(W1, DIM, NOUT, 0);
    transpose_kernel<<<dim3(NOUT / 32, NOUT / 32), tb>>>(W2, NOUT, NOUT, 1);

    dim3 grid(NOUT / BN, BATCH / BM);   // (32, 256)
    gemm_kernel<DIM, true><<<grid, 128, DYN_SMEM>>>(b1, nullptr);
    gemm_kernel<NOUT, false><<<grid, 128, DYN_SMEM>>>(b2, out);
}